// round 3
// baseline (speedup 1.0000x reference)
#include <cuda_runtime.h>

#define RB 64
#define CB 64
#define NROWS 8192
#define TCOLS 8192
#define T4 (TCOLS / 4)        // 2048 float4 per row
#define NCHUNK 8              // 1024 columns (256 float4) per chunk
#define NSPLIT 2              // row halves per row-block
#define NPART (NCHUNK * NSPLIT)

__device__ int   g_row_start[RB + 1];
__device__ float g_row_cnt[RB];
__device__ float g_col_cnt[CB];
__device__ float g_partial[RB][NPART][CB];

// ---------------------------------------------------------------------------
// Kernel 1: segment counts from sorted ids, exclusive-scan boundaries,
// emit cumsums as FLOAT VALUES into the output tail:
//   out[0..4095]      propensity (float32, written by k_mlp)
//   out[4096..4160]   row_cumsum (65 values, stored as float)
//   out[4161..4225]   col_cumsum (65 values, stored as float)
// ---------------------------------------------------------------------------
__global__ void k_bounds(const int* __restrict__ row_ids,
                         const int* __restrict__ col_ids,
                         float* __restrict__ out) {
    __shared__ int rc[RB];
    __shared__ int cc[CB];
    int tid = threadIdx.x;
    if (tid < RB) rc[tid] = 0;
    if (tid < CB) cc[tid] = 0;
    __syncthreads();
    for (int i = tid; i < NROWS; i += blockDim.x) atomicAdd(&rc[row_ids[i]], 1);
    for (int i = tid; i < TCOLS; i += blockDim.x) atomicAdd(&cc[col_ids[i]], 1);
    __syncthreads();
    if (tid == 0) {
        int s = 0;
        for (int k = 0; k < RB; k++) {
            g_row_start[k] = s;
            out[RB * CB + k] = (float)s;
            s += rc[k];
        }
        g_row_start[RB] = s;
        out[RB * CB + RB] = (float)s;
        s = 0;
        for (int k = 0; k < CB; k++) {
            out[RB * CB + 65 + k] = (float)s;
            s += cc[k];
        }
        out[RB * CB + 65 + CB] = (float)s;
    }
    if (tid < RB) g_row_cnt[tid] = (float)rc[tid];
    if (tid < CB) g_col_cnt[tid] = (float)cc[tid];
}

// ---------------------------------------------------------------------------
// Kernel 2: streaming column-strip reduction.
// Block = (chunk, rb, half). Thread owns one float4 column group; sums down
// the rows of its half of row-block rb. Fully coalesced LDG.128 stream.
// Reduce per-column sums into shared acc[CB], write deterministic partials.
// ---------------------------------------------------------------------------
__global__ __launch_bounds__(256) void k_sum(const float* __restrict__ X,
                                             const int* __restrict__ col_ids) {
    int chunk = blockIdx.x;            // 0..NCHUNK-1
    int rb    = blockIdx.y;            // 0..RB-1
    int half  = blockIdx.z;            // 0..NSPLIT-1
    int r0 = g_row_start[rb];
    int r1 = g_row_start[rb + 1];
    int len = r1 - r0;
    int h0 = r0 + (len * half) / NSPLIT;
    int h1 = r0 + (len * (half + 1)) / NSPLIT;

    int c4 = chunk * 256 + threadIdx.x;          // float4 column index
    const float4* __restrict__ Xp = (const float4*)X;

    float ax = 0.f, ay = 0.f, az = 0.f, aw = 0.f;
    int base = h0 * T4 + c4;
    int n = h0;
    // unroll-by-4 over rows for MLP
    for (; n + 4 <= h1; n += 4, base += 4 * T4) {
        float4 v0 = Xp[base];
        float4 v1 = Xp[base + T4];
        float4 v2 = Xp[base + 2 * T4];
        float4 v3 = Xp[base + 3 * T4];
        ax += v0.x + v1.x + v2.x + v3.x;
        ay += v0.y + v1.y + v2.y + v3.y;
        az += v0.z + v1.z + v2.z + v3.z;
        aw += v0.w + v1.w + v2.w + v3.w;
    }
    for (; n < h1; n++, base += T4) {
        float4 v = Xp[base];
        ax += v.x; ay += v.y; az += v.z; aw += v.w;
    }

    __shared__ float sacc[CB];
    if (threadIdx.x < CB) sacc[threadIdx.x] = 0.f;
    __syncthreads();

    int t = c4 * 4;
    int cb0 = col_ids[t];
    int cb3 = col_ids[t + 3];
    if (cb0 == cb3) {
        atomicAdd(&sacc[cb0], ax + ay + az + aw);
    } else {
        int cb1 = col_ids[t + 1];
        int cb2 = col_ids[t + 2];
        atomicAdd(&sacc[cb0], ax);
        atomicAdd(&sacc[cb1], ay);
        atomicAdd(&sacc[cb2], az);
        atomicAdd(&sacc[cb3], aw);
    }
    __syncthreads();
    if (threadIdx.x < CB)
        g_partial[rb][chunk * NSPLIT + half][threadIdx.x] = sacc[threadIdx.x];
}

// ---------------------------------------------------------------------------
// Kernel 3: fold partials -> block mean -> 1->3->3->1 relu MLP -> sigmoid.
// ---------------------------------------------------------------------------
__global__ void k_mlp(const float* __restrict__ W1, const float* __restrict__ b1,
                      const float* __restrict__ W2, const float* __restrict__ b2,
                      const float* __restrict__ W3, const float* __restrict__ b3,
                      float* __restrict__ out) {
    int idx = blockIdx.x * blockDim.x + threadIdx.x;
    if (idx >= RB * CB) return;
    int rb = idx / CB;
    int cb = idx % CB;
    float s = 0.f;
#pragma unroll
    for (int j = 0; j < NPART; j++) s += g_partial[rb][j][cb];
    float x = s / (g_row_cnt[rb] * g_col_cnt[cb]);

    float h1[3], h2[3];
#pragma unroll
    for (int j = 0; j < 3; j++) h1[j] = fmaxf(x * W1[j] + b1[j], 0.f);
#pragma unroll
    for (int j = 0; j < 3; j++) {
        float v = b2[j];
#pragma unroll
        for (int i = 0; i < 3; i++) v += h1[i] * W2[i * 3 + j];
        h2[j] = fmaxf(v, 0.f);
    }
    float o = b3[0];
#pragma unroll
    for (int i = 0; i < 3; i++) o += h2[i] * W3[i];
    out[idx] = 1.f / (1.f + __expf(-o));
}

extern "C" void kernel_launch(void* const* d_in, const int* in_sizes, int n_in,
                              void* d_out, int out_size) {
    const float* X       = (const float*)d_in[0];
    const int*   row_ids = (const int*)d_in[1];
    const int*   col_ids = (const int*)d_in[2];
    const float* W1      = (const float*)d_in[3];
    const float* b1      = (const float*)d_in[4];
    const float* W2      = (const float*)d_in[5];
    const float* b2      = (const float*)d_in[6];
    const float* W3      = (const float*)d_in[7];
    const float* b3      = (const float*)d_in[8];
    float* out = (float*)d_out;

    k_bounds<<<1, 256>>>(row_ids, col_ids, out);
    k_sum<<<dim3(NCHUNK, RB, NSPLIT), 256>>>(X, col_ids);
    k_mlp<<<(RB * CB + 255) / 256, 256>>>(W1, b1, W2, b2, W3, b3, out);
}